// round 2
// baseline (speedup 1.0000x reference)
#include <cuda_runtime.h>
#include <math.h>

#define BB 4
#define NN 512
#define HD 64
#define IDM 128
#define PI_F 3.14159265358979323846f
#define INV_SQRT2 0.70710678118654752440f
#define MWARPS 4

// Scratch (device globals: no allocation allowed)
__device__ float g_U2[BB*NN*IDM];   // (A@We1 + be1) * (1/sqrt2)
__device__ float g_V2[BB*NN*IDM];   // (C@We1)       * (1/sqrt2)
__device__ float g_SU[BB*NN];       // sum_k 0.5*w2[k]*U[k]  (== dot(U2, w2/sqrt2))
__device__ float g_SV[BB*NN];

// ---------------------------------------------------------------------------
// Precompute: feats -> A/C pre-activations -> U,V rows (+ linear-GELU scalars)
// One block per (b,n) row, 128 threads.
// ---------------------------------------------------------------------------
__global__ __launch_bounds__(128) void prep_kernel(
    const float* __restrict__ bf,   const float* __restrict__ emb,
    const float* __restrict__ Wcls, const float* __restrict__ bcls,
    const float* __restrict__ Wpos, const float* __restrict__ bpos,
    const float* __restrict__ Win,  const float* __restrict__ bin,
    const float* __restrict__ Wout, const float* __restrict__ bout,
    const float* __restrict__ We1,  const float* __restrict__ be1,
    const float* __restrict__ We2)
{
    int row = blockIdx.x;          // b*NN + n
    int t = threadIdx.x;
    __shared__ float feats[HD];
    __shared__ float Apre[IDM], Bpre[IDM];
    __shared__ float red[IDM];

    // sample-point position embedding (2 values), faithful to reference
    float ang = emb[row*2 + 0] * PI_F;
    float rho = emb[row*2 + 1] * 800.0f;
    float tn = tanf(ang);
    float ic = 1.0f / cosf(ang);
    float lin1 = (1.0f - 1e-5f) / 71.0f;
    float y0 = 160.0f;
    float y1 = 160.0f - lin1 * 320.0f;
    float p0 = (-tn * y0 + rho * ic) * (1.0f / 800.0f);
    float p1 = (-tn * y1 + rho * ic) * (1.0f / 800.0f);

    const float* x = bf + row * HD;
    if (t < HD) {
        float acc = bcls[t];
        #pragma unroll 8
        for (int k = 0; k < HD; k++) acc = fmaf(x[k], Wcls[k*HD + t], acc);
        feats[t] = fmaxf(acc, 0.0f);
    }
    __syncthreads();
    {
        float ain = bin[t], aout = bout[t];
        #pragma unroll 8
        for (int k = 0; k < HD; k++) {
            float f = feats[k];
            ain  = fmaf(f, Win [k*IDM + t], ain);
            aout = fmaf(f, Wout[k*IDM + t], aout);
        }
        float pe = fmaf(p0, Wpos[t], p1 * Wpos[IDM + t]);
        Apre[t] = ain + pe + bpos[t];   // f_in + pos@Wpos + bpos
        Bpre[t] = aout + pe;            // f_out + pos@Wpos
    }
    __syncthreads();
    float u = be1[t], v = 0.0f;
    #pragma unroll 8
    for (int k = 0; k < IDM; k++) {
        float w = We1[k*IDM + t];
        u = fmaf(Apre[k], w, u);
        v = fmaf(Bpre[k], w, v);
    }
    float u2 = u * INV_SQRT2;
    float v2 = v * INV_SQRT2;
    g_U2[row*IDM + t] = u2;
    g_V2[row*IDM + t] = v2;

    float w2s = We2[t] * INV_SQRT2;   // so that dot(U2, w2s) == sum 0.5*w2*U
    red[t] = u2 * w2s;
    __syncthreads();
    if (t < 32) {
        float s = red[t] + red[t+32] + red[t+64] + red[t+96];
        #pragma unroll
        for (int o = 16; o; o >>= 1) s += __shfl_xor_sync(0xffffffffu, s, o);
        if (t == 0) g_SU[row] = s;
    }
    __syncthreads();
    red[t] = v2 * w2s;
    __syncthreads();
    if (t < 32) {
        float s = red[t] + red[t+32] + red[t+64] + red[t+96];
        #pragma unroll
        for (int o = 16; o; o >>= 1) s += __shfl_xor_sync(0xffffffffu, s, o);
        if (t == 0) g_SV[row] = s;
    }
}

// ---------------------------------------------------------------------------
// Main: one warp per output column (b,j). Lanes span the 128 I-dim (4 each).
// edge_val(i,j) = su[i] - sv[j] + be2 + sum_k (U2[i,k]-V2[j,k])*w2s[k]*erf(U2-V2)
// node_max[j] = max(0, max over allowed i), then 64->64->1 MLP + sigmoid.
// ---------------------------------------------------------------------------
__global__ __launch_bounds__(32*MWARPS) void main_kernel(
    const float* __restrict__ cls, const int* __restrict__ aid,
    const float* __restrict__ emb,
    const float* __restrict__ We2, const float* __restrict__ be2,
    const float* __restrict__ Wn1, const float* __restrict__ bn1,
    const float* __restrict__ Wn2, const float* __restrict__ bn2,
    const float* __restrict__ Wh,  const float* __restrict__ bh,
    float* __restrict__ out)
{
    __shared__ float cls_s[NN], ang_s[NN], su_s[NN];
    __shared__ int   id_s[NN];
    __shared__ unsigned short list_s[MWARPS][NN];
    __shared__ float n1_s[MWARPS][HD];

    int t = threadIdx.x, lane = t & 31, w = t >> 5;
    int g0 = blockIdx.x * MWARPS;
    int b  = g0 >> 9;                  // blocks never straddle a batch (512 % MWARPS == 0)

    for (int i = t; i < NN; i += 32*MWARPS) {
        cls_s[i] = cls[b*NN + i];
        ang_s[i] = emb[(b*NN + i)*2] * PI_F;
        id_s[i]  = aid[b*NN + i];
        su_s[i]  = g_SU[b*NN + i];
    }
    __syncthreads();

    int g = g0 + w;
    int j = g & 511;
    float cj = cls_s[j];
    if (cj < 0.4f) {                   // sigmoid(-1e6) == 0 in f32
        if (lane == 0) out[g] = 0.0f;
        return;
    }
    float aj  = ang_s[j];
    int   idj = id_s[j];

    float4 v4  = *(const float4*)(g_V2 + (size_t)g*IDM + lane*4);
    float4 w2r = *(const float4*)(We2 + lane*4);
    float w2sx = w2r.x*INV_SQRT2, w2sy = w2r.y*INV_SQRT2;
    float w2sz = w2r.z*INV_SQRT2, w2sw = w2r.w*INV_SQRT2;
    float cconst = be2[0] - g_SV[g];

    // ballot-compacted list of allowed i for this column
    unsigned short* lst = list_s[w];
    int cnt = 0;
    for (int c = 0; c < NN; c += 32) {
        int i = c + lane;
        float ci = cls_s[i];
        bool p = (fabsf(ang_s[i] - aj) < 0.5f) &&
                 ((ci > cj) || ((ci == cj) && (id_s[i] > idj)));
        unsigned m = __ballot_sync(0xffffffffu, p);
        if (p) lst[cnt + __popc(m & ((1u << lane) - 1u))] = (unsigned short)i;
        cnt += __popc(m);
    }
    __syncwarp();

    const float* Ub = g_U2 + (size_t)b*NN*IDM + lane*4;
    float runmax = 0.0f;               // diagonal supress==0 guarantees a 0 entry
    if (cnt > 0) {
        int icur = lst[0];
        float4 u = *(const float4*)(Ub + icur*IDM);
        float su_cur = su_s[icur];
        for (int p = 0; p < cnt; p++) {
            float4 un = make_float4(0.f, 0.f, 0.f, 0.f);
            float su_n = 0.0f;
            if (p + 1 < cnt) {         // prefetch next U row
                int inx = lst[p + 1];
                un   = *(const float4*)(Ub + inx*IDM);
                su_n = su_s[inx];
            }
            float dx = u.x - v4.x, dy = u.y - v4.y;
            float dz = u.z - v4.z, dw = u.w - v4.w;
            float s;
            s = (dx * w2sx) * erff(dx);
            s = fmaf(dy * w2sy, erff(dy), s);
            s = fmaf(dz * w2sz, erff(dz), s);
            s = fmaf(dw * w2sw, erff(dw), s);
            #pragma unroll
            for (int o = 16; o; o >>= 1) s += __shfl_xor_sync(0xffffffffu, s, o);
            runmax = fmaxf(runmax, s + su_cur + cconst);
            u = un; su_cur = su_n;
        }
    }

    // node MLP: relu(nm*Wn1+bn1) -> relu(@Wn2+bn2) -> @Wh + bh -> sigmoid
    float nm = runmax;
    float n1a = fmaxf(fmaf(nm, Wn1[lane],      bn1[lane]),      0.0f);
    float n1b = fmaxf(fmaf(nm, Wn1[lane + 32], bn1[lane + 32]), 0.0f);
    n1_s[w][lane]      = n1a;
    n1_s[w][lane + 32] = n1b;
    __syncwarp();
    float acc0 = bn2[lane], acc1 = bn2[lane + 32];
    #pragma unroll 8
    for (int k = 0; k < HD; k++) {
        float f = n1_s[w][k];
        acc0 = fmaf(f, Wn2[k*HD + lane],      acc0);
        acc1 = fmaf(f, Wn2[k*HD + lane + 32], acc1);
    }
    acc0 = fmaxf(acc0, 0.0f);
    acc1 = fmaxf(acc1, 0.0f);
    float part = fmaf(acc0, Wh[lane], acc1 * Wh[lane + 32]);
    #pragma unroll
    for (int o = 16; o; o >>= 1) part += __shfl_xor_sync(0xffffffffu, part, o);
    if (lane == 0) {
        float lg = part + bh[0];
        out[g] = 1.0f / (1.0f + expf(-lg));
    }
}

extern "C" void kernel_launch(void* const* d_in, const int* in_sizes, int n_in,
                              void* d_out, int out_size) {
    const float* bf   = (const float*)d_in[0];
    const float* cls  = (const float*)d_in[1];
    const int*   aid  = (const int*)  d_in[2];
    const float* emb  = (const float*)d_in[3];
    const float* Wcls = (const float*)d_in[4];
    const float* bcls = (const float*)d_in[5];
    const float* Wpos = (const float*)d_in[6];
    const float* bpos = (const float*)d_in[7];
    const float* Win  = (const float*)d_in[8];
    const float* bin  = (const float*)d_in[9];
    const float* Wout = (const float*)d_in[10];
    const float* bout = (const float*)d_in[11];
    const float* We1  = (const float*)d_in[12];
    const float* be1  = (const float*)d_in[13];
    const float* We2  = (const float*)d_in[14];
    const float* be2  = (const float*)d_in[15];
    const float* Wn1  = (const float*)d_in[16];
    const float* bn1  = (const float*)d_in[17];
    const float* Wn2  = (const float*)d_in[18];
    const float* bn2  = (const float*)d_in[19];
    const float* Wh   = (const float*)d_in[20];
    const float* bh   = (const float*)d_in[21];
    float* out = (float*)d_out;

    prep_kernel<<<BB*NN, 128>>>(bf, emb, Wcls, bcls, Wpos, bpos,
                                Win, bin, Wout, bout, We1, be1, We2);
    main_kernel<<<(BB*NN)/MWARPS, 32*MWARPS>>>(cls, aid, emb, We2, be2,
                                               Wn1, bn1, Wn2, bn2, Wh, bh, out);
}

// round 4
// speedup vs baseline: 1.5151x; 1.5151x over previous
#include <cuda_runtime.h>
#include <math.h>

#define BB 4
#define NN 512
#define HD 64
#define IDM 128
#define PI_F 3.14159265358979323846f
#define INV_SQRT2 0.70710678118654752440f
#define RPB 8            // rows per prep block
#define CPB 4            // columns per main block
#define SPLIT 4          // warps per column

// Scratch (device globals: no allocation allowed)
__device__ float g_U2[BB*NN*IDM];   // (A@We1 + be1) / sqrt2
__device__ float g_V2[BB*NN*IDM];   // (C@We1)       / sqrt2
__device__ float g_SU[BB*NN];       // 0.5 * dot(U, w2)
__device__ float g_SV[BB*NN];

// ---------------------------------------------------------------------------
// Precompute. One block per 8 rows, 128 threads (t = I-dim index).
// Weights loaded once per block, 16 FMA per weight load.
// ---------------------------------------------------------------------------
__global__ __launch_bounds__(128) void prep_kernel(
    const float* __restrict__ bf,   const float* __restrict__ emb,
    const float* __restrict__ Wcls, const float* __restrict__ bcls,
    const float* __restrict__ Wpos, const float* __restrict__ bpos,
    const float* __restrict__ Win,  const float* __restrict__ bin,
    const float* __restrict__ Wout, const float* __restrict__ bout,
    const float* __restrict__ We1,  const float* __restrict__ be1,
    const float* __restrict__ We2)
{
    int t = threadIdx.x, lane = t & 31, wid = t >> 5;
    int row0 = blockIdx.x * RPB;

    __shared__ float xs[RPB][HD];        // input rows
    __shared__ float featsT[HD][RPB];    // feats, k-major
    __shared__ float ApreT[IDM][RPB];    // pre-GELU inputs, k-major
    __shared__ float BpreT[IDM][RPB];
    __shared__ float p0s[RPB], p1s[RPB];
    __shared__ float partU[4][RPB], partV[4][RPB];

    // load the 8 input rows (coalesced)
    for (int idx = t; idx < RPB*HD; idx += 128)
        ((float*)xs)[idx] = bf[row0*HD + idx];

    // sample-point position values per row (faithful to reference)
    if (t < RPB) {
        int row = row0 + t;
        float ang = emb[row*2 + 0] * PI_F;
        float rho = emb[row*2 + 1] * 800.0f;
        float tn = tanf(ang);
        float ic = 1.0f / cosf(ang);
        float lin1 = (1.0f - 1e-5f) / 71.0f;
        float y0 = 160.0f;
        float y1 = 160.0f - lin1 * 320.0f;
        p0s[t] = (-tn * y0 + rho * ic) * (1.0f / 800.0f);
        p1s[t] = (-tn * y1 + rho * ic) * (1.0f / 800.0f);
    }
    __syncthreads();

    // phase 1: feats = relu(x @ Wcls + bcls), two rows per pass
    {
        int rhalf = t >> 6, d = t & 63;
        float bc = bcls[d];
        #pragma unroll
        for (int pass = 0; pass < RPB; pass += 2) {
            int r = pass + rhalf;
            float acc = bc;
            #pragma unroll 8
            for (int k = 0; k < HD; k++) acc = fmaf(xs[r][k], Wcls[k*HD + d], acc);
            featsT[d][r] = fmaxf(acc, 0.0f);
        }
    }
    __syncthreads();

    // phase 2: f_in / f_out for all 8 rows
    float ain[RPB], aout[RPB];
    {
        float bi = bin[t], bo = bout[t];
        #pragma unroll
        for (int r = 0; r < RPB; r++) { ain[r] = bi; aout[r] = bo; }
        for (int k = 0; k < HD; k++) {
            float win  = Win [k*IDM + t];
            float wout = Wout[k*IDM + t];
            float4 fa = *(const float4*)&featsT[k][0];
            float4 fb = *(const float4*)&featsT[k][4];
            ain[0] = fmaf(fa.x, win, ain[0]);  aout[0] = fmaf(fa.x, wout, aout[0]);
            ain[1] = fmaf(fa.y, win, ain[1]);  aout[1] = fmaf(fa.y, wout, aout[1]);
            ain[2] = fmaf(fa.z, win, ain[2]);  aout[2] = fmaf(fa.z, wout, aout[2]);
            ain[3] = fmaf(fa.w, win, ain[3]);  aout[3] = fmaf(fa.w, wout, aout[3]);
            ain[4] = fmaf(fb.x, win, ain[4]);  aout[4] = fmaf(fb.x, wout, aout[4]);
            ain[5] = fmaf(fb.y, win, ain[5]);  aout[5] = fmaf(fb.y, wout, aout[5]);
            ain[6] = fmaf(fb.z, win, ain[6]);  aout[6] = fmaf(fb.z, wout, aout[6]);
            ain[7] = fmaf(fb.w, win, ain[7]);  aout[7] = fmaf(fb.w, wout, aout[7]);
        }
        float wp0 = Wpos[t], wp1 = Wpos[IDM + t], bp = bpos[t];
        #pragma unroll
        for (int r = 0; r < RPB; r++) {
            float pe = fmaf(p0s[r], wp0, p1s[r] * wp1);
            ApreT[t][r] = ain[r] + pe + bp;   // f_in + pos@Wpos + bpos
            BpreT[t][r] = aout[r] + pe;       // f_out + pos@Wpos
        }
    }
    __syncthreads();

    // phase 3: U = Apre @ We1 + be1, V = Bpre @ We1
    float u[RPB], v[RPB];
    {
        float b1 = be1[t];
        #pragma unroll
        for (int r = 0; r < RPB; r++) { u[r] = b1; v[r] = 0.0f; }
        for (int k = 0; k < IDM; k++) {
            float w = We1[k*IDM + t];
            float4 a0 = *(const float4*)&ApreT[k][0];
            float4 a1 = *(const float4*)&ApreT[k][4];
            float4 c0 = *(const float4*)&BpreT[k][0];
            float4 c1 = *(const float4*)&BpreT[k][4];
            u[0] = fmaf(a0.x, w, u[0]);  v[0] = fmaf(c0.x, w, v[0]);
            u[1] = fmaf(a0.y, w, u[1]);  v[1] = fmaf(c0.y, w, v[1]);
            u[2] = fmaf(a0.z, w, u[2]);  v[2] = fmaf(c0.z, w, v[2]);
            u[3] = fmaf(a0.w, w, u[3]);  v[3] = fmaf(c0.w, w, v[3]);
            u[4] = fmaf(a1.x, w, u[4]);  v[4] = fmaf(c1.x, w, v[4]);
            u[5] = fmaf(a1.y, w, u[5]);  v[5] = fmaf(c1.y, w, v[5]);
            u[6] = fmaf(a1.z, w, u[6]);  v[6] = fmaf(c1.z, w, v[6]);
            u[7] = fmaf(a1.w, w, u[7]);  v[7] = fmaf(c1.w, w, v[7]);
        }
    }

    // store U2/V2 and reduce SU/SV
    float w2s = We2[t] * INV_SQRT2;
    #pragma unroll
    for (int r = 0; r < RPB; r++) {
        float u2 = u[r] * INV_SQRT2;
        float v2 = v[r] * INV_SQRT2;
        g_U2[(row0 + r)*IDM + t] = u2;
        g_V2[(row0 + r)*IDM + t] = v2;
        float su = u2 * w2s, sv = v2 * w2s;
        #pragma unroll
        for (int o = 16; o; o >>= 1) {
            su += __shfl_xor_sync(0xffffffffu, su, o);
            sv += __shfl_xor_sync(0xffffffffu, sv, o);
        }
        if (lane == 0) { partU[wid][r] = su; partV[wid][r] = sv; }
    }
    __syncthreads();
    if (t < RPB)
        g_SU[row0 + t] = partU[0][t] + partU[1][t] + partU[2][t] + partU[3][t];
    else if (t < 2*RPB) {
        int r = t - RPB;
        g_SV[row0 + r] = partV[0][r] + partV[1][r] + partV[2][r] + partV[3][r];
    }
}

// ---------------------------------------------------------------------------
// Main: 4 columns per block, 4 split-warps per column (512 threads).
// Each split warp processes every 4th allowed i; partial maxes merged in smem.
// ---------------------------------------------------------------------------
__global__ __launch_bounds__(512) void main_kernel(
    const float* __restrict__ cls, const int* __restrict__ aid,
    const float* __restrict__ emb,
    const float* __restrict__ We2, const float* __restrict__ be2,
    const float* __restrict__ Wn1, const float* __restrict__ bn1,
    const float* __restrict__ Wn2, const float* __restrict__ bn2,
    const float* __restrict__ Wh,  const float* __restrict__ bh,
    float* __restrict__ out)
{
    __shared__ float cls_s[NN], ang_s[NN], su_s[NN];
    __shared__ int   id_s[NN];
    __shared__ unsigned short list_s[CPB][NN];
    __shared__ float wn2_s[HD*HD];
    __shared__ float pmax_s[CPB][SPLIT];
    __shared__ float n1_s[CPB][HD];

    int t = threadIdx.x, lane = t & 31, w = t >> 5;
    int col = w >> 2, sw = w & 3;
    int g0 = blockIdx.x * CPB;
    int b  = g0 >> 9;                  // 128 blocks per batch, never straddles

    for (int i = t; i < NN; i += 512) {
        cls_s[i] = cls[b*NN + i];
        ang_s[i] = emb[(b*NN + i)*2] * PI_F;
        id_s[i]  = aid[b*NN + i];
        su_s[i]  = g_SU[b*NN + i];
    }
    for (int i = t; i < HD*HD; i += 512) wn2_s[i] = Wn2[i];
    __syncthreads();

    int g = g0 + col;
    int j = g & 511;
    float cj = cls_s[j];
    bool alive = (cj >= 0.4f);         // sigmoid(-1e6) == 0 in f32
    float runmax = 0.0f;               // diagonal guarantees a 0 entry

    if (alive) {
        float aj  = ang_s[j];
        int   idj = id_s[j];

        // all 4 split-warps build the identical compacted list (benign race)
        unsigned short* lst = list_s[col];
        int cnt = 0;
        for (int c = 0; c < NN; c += 32) {
            int i = c + lane;
            float ci = cls_s[i];
            bool p = (fabsf(ang_s[i] - aj) < 0.5f) &&
                     ((ci > cj) || ((ci == cj) && (id_s[i] > idj)));
            unsigned m = __ballot_sync(0xffffffffu, p);
            if (p) lst[cnt + __popc(m & ((1u << lane) - 1u))] = (unsigned short)i;
            cnt += __popc(m);
        }
        __syncwarp();

        float4 v4  = *(const float4*)(g_V2 + (size_t)g*IDM + lane*4);
        float4 w2r = *(const float4*)(We2 + lane*4);
        float w2sx = w2r.x*INV_SQRT2, w2sy = w2r.y*INV_SQRT2;
        float w2sz = w2r.z*INV_SQRT2, w2sw = w2r.w*INV_SQRT2;
        float cconst = be2[0] - g_SV[g];

        const float* Ub = g_U2 + (size_t)b*NN*IDM + lane*4;

        // 2 list entries per iteration: independent shuffle chains for ILP
        for (int p = sw; p < cnt; p += 2*SPLIT) {
            int i0 = lst[p];
            int pn = p + SPLIT;
            bool h1 = (pn < cnt);
            int i1 = h1 ? lst[pn] : i0;
            float4 u0 = *(const float4*)(Ub + i0*IDM);
            float4 u1 = *(const float4*)(Ub + i1*IDM);
            float su0 = su_s[i0], su1 = su_s[i1];

            float dx = u0.x - v4.x, dy = u0.y - v4.y;
            float dz = u0.z - v4.z, dw = u0.w - v4.w;
            float s0;
            s0 = (dx * w2sx) * erff(dx);
            s0 = fmaf(dy * w2sy, erff(dy), s0);
            s0 = fmaf(dz * w2sz, erff(dz), s0);
            s0 = fmaf(dw * w2sw, erff(dw), s0);

            float ex = u1.x - v4.x, ey = u1.y - v4.y;
            float ez = u1.z - v4.z, ew = u1.w - v4.w;
            float s1;
            s1 = (ex * w2sx) * erff(ex);
            s1 = fmaf(ey * w2sy, erff(ey), s1);
            s1 = fmaf(ez * w2sz, erff(ez), s1);
            s1 = fmaf(ew * w2sw, erff(ew), s1);

            #pragma unroll
            for (int o = 16; o; o >>= 1) {
                s0 += __shfl_xor_sync(0xffffffffu, s0, o);
                s1 += __shfl_xor_sync(0xffffffffu, s1, o);
            }
            runmax = fmaxf(runmax, s0 + su0 + cconst);
            if (h1) runmax = fmaxf(runmax, s1 + su1 + cconst);
        }
    }
    if (lane == 0) pmax_s[col][sw] = runmax;
    __syncthreads();

    // final: one warp per column does the node MLP
    if (sw == 0) {
        if (!alive) {
            if (lane == 0) out[g] = 0.0f;
        } else {
            float nm = fmaxf(fmaxf(pmax_s[col][0], pmax_s[col][1]),
                             fmaxf(pmax_s[col][2], pmax_s[col][3]));
            float n1a = fmaxf(fmaf(nm, Wn1[lane],      bn1[lane]),      0.0f);
            float n1b = fmaxf(fmaf(nm, Wn1[lane + 32], bn1[lane + 32]), 0.0f);
            n1_s[col][lane]      = n1a;
            n1_s[col][lane + 32] = n1b;
            __syncwarp();
            float acc0 = bn2[lane], acc1 = bn2[lane + 32];
            #pragma unroll 8
            for (int k = 0; k < HD; k++) {
                float f = n1_s[col][k];
                acc0 = fmaf(f, wn2_s[k*HD + lane],      acc0);
                acc1 = fmaf(f, wn2_s[k*HD + lane + 32], acc1);
            }
            acc0 = fmaxf(acc0, 0.0f);
            acc1 = fmaxf(acc1, 0.0f);
            float part = fmaf(acc0, Wh[lane], acc1 * Wh[lane + 32]);
            #pragma unroll
            for (int o = 16; o; o >>= 1) part += __shfl_xor_sync(0xffffffffu, part, o);
            if (lane == 0) {
                float lg = part + bh[0];
                out[g] = 1.0f / (1.0f + expf(-lg));
            }
        }
    }
}

extern "C" void kernel_launch(void* const* d_in, const int* in_sizes, int n_in,
                              void* d_out, int out_size) {
    const float* bf   = (const float*)d_in[0];
    const float* cls  = (const float*)d_in[1];
    const int*   aid  = (const int*)  d_in[2];
    const float* emb  = (const float*)d_in[3];
    const float* Wcls = (const float*)d_in[4];
    const float* bcls = (const float*)d_in[5];
    const float* Wpos = (const float*)d_in[6];
    const float* bpos = (const float*)d_in[7];
    const float* Win  = (const float*)d_in[8];
    const float* bin  = (const float*)d_in[9];
    const float* Wout = (const float*)d_in[10];
    const float* bout = (const float*)d_in[11];
    const float* We1  = (const float*)d_in[12];
    const float* be1  = (const float*)d_in[13];
    const float* We2  = (const float*)d_in[14];
    const float* be2  = (const float*)d_in[15];
    const float* Wn1  = (const float*)d_in[16];
    const float* bn1  = (const float*)d_in[17];
    const float* Wn2  = (const float*)d_in[18];
    const float* bn2  = (const float*)d_in[19];
    const float* Wh   = (const float*)d_in[20];
    const float* bh   = (const float*)d_in[21];
    float* out = (float*)d_out;

    prep_kernel<<<(BB*NN)/RPB, 128>>>(bf, emb, Wcls, bcls, Wpos, bpos,
                                      Win, bin, Wout, bout, We1, be1, We2);
    main_kernel<<<(BB*NN)/CPB, 512>>>(cls, aid, emb, We2, be2,
                                      Wn1, bn1, Wn2, bn2, Wh, bh, out);
}

// round 6
// speedup vs baseline: 2.4375x; 1.6088x over previous
#include <cuda_runtime.h>
#include <math.h>

#define BB 4
#define NN 512
#define HD 64
#define IDM 128
#define PI_F 3.14159265358979323846f
#define INV_SQRT2 0.70710678118654752440f
#define RPB 8            // rows per prep block
#define CPB 4            // columns per main block
#define SPLIT 4          // warps per column

// tanh-based erf approx constants: erf(d) ~= tanh(C0*d + C1*d^3)
#define ERF_C0 1.1283791671f
#define ERF_C1 0.1009052923f

// Scratch (device globals: no allocation allowed)
__device__ float g_U2[BB*NN*IDM];   // (A@We1 + be1) / sqrt2
__device__ float g_V2[BB*NN*IDM];   // (C@We1)       / sqrt2
__device__ float g_SU[BB*NN];       // 0.5 * dot(U, w2)
__device__ float g_SV[BB*NN];

typedef unsigned long long u64;

__device__ __forceinline__ u64 pack2(float lo, float hi) {
    u64 r; asm("mov.b64 %0, {%1, %2};" : "=l"(r) : "f"(lo), "f"(hi)); return r;
}
__device__ __forceinline__ void unpack2(u64 v, float& lo, float& hi) {
    asm("mov.b64 {%0, %1}, %2;" : "=f"(lo), "=f"(hi) : "l"(v));
}
__device__ __forceinline__ u64 fma2(u64 a, u64 b, u64 c) {
    u64 r; asm("fma.rn.f32x2 %0, %1, %2, %3;" : "=l"(r) : "l"(a), "l"(b), "l"(c)); return r;
}
__device__ __forceinline__ u64 add2(u64 a, u64 b) {
    u64 r; asm("add.rn.f32x2 %0, %1, %2;" : "=l"(r) : "l"(a), "l"(b)); return r;
}
__device__ __forceinline__ u64 mul2(u64 a, u64 b) {
    u64 r; asm("mul.rn.f32x2 %0, %1, %2;" : "=l"(r) : "l"(a), "l"(b)); return r;
}
__device__ __forceinline__ float fast_tanh(float x) {
    float y; asm("tanh.approx.f32 %0, %1;" : "=f"(y) : "f"(x)); return y;
}

// ---------------------------------------------------------------------------
// Precompute. One block per 8 rows, 128 threads (t = I-dim index).
// Phases 2/3 use packed f32x2 FMA (2 rows per instruction).
// ---------------------------------------------------------------------------
__global__ __launch_bounds__(128) void prep_kernel(
    const float* __restrict__ bf,   const float* __restrict__ emb,
    const float* __restrict__ Wcls, const float* __restrict__ bcls,
    const float* __restrict__ Wpos, const float* __restrict__ bpos,
    const float* __restrict__ Win,  const float* __restrict__ bin,
    const float* __restrict__ Wout, const float* __restrict__ bout,
    const float* __restrict__ We1,  const float* __restrict__ be1,
    const float* __restrict__ We2)
{
    int t = threadIdx.x, lane = t & 31, wid = t >> 5;
    int row0 = blockIdx.x * RPB;

    __shared__ __align__(16) float xs[RPB][HD];
    __shared__ __align__(16) float featsT[HD][RPB];   // k-major
    __shared__ __align__(16) float ApreT[IDM][RPB];   // k-major
    __shared__ __align__(16) float BpreT[IDM][RPB];
    __shared__ float p0s[RPB], p1s[RPB];
    __shared__ float partU[4][RPB], partV[4][RPB];

    for (int idx = t; idx < RPB*HD; idx += 128)
        ((float*)xs)[idx] = bf[row0*HD + idx];

    if (t < RPB) {
        int row = row0 + t;
        float ang = emb[row*2 + 0] * PI_F;
        float rho = emb[row*2 + 1] * 800.0f;
        float tn = tanf(ang);
        float ic = 1.0f / cosf(ang);
        float lin1 = (1.0f - 1e-5f) / 71.0f;
        float y0 = 160.0f;
        float y1 = 160.0f - lin1 * 320.0f;
        p0s[t] = (-tn * y0 + rho * ic) * (1.0f / 800.0f);
        p1s[t] = (-tn * y1 + rho * ic) * (1.0f / 800.0f);
    }
    __syncthreads();

    // phase 1: feats = relu(x @ Wcls + bcls), two rows per pass
    {
        int rhalf = t >> 6, d = t & 63;
        float bc = bcls[d];
        #pragma unroll
        for (int pass = 0; pass < RPB; pass += 2) {
            int r = pass + rhalf;
            float acc = bc;
            #pragma unroll 8
            for (int k = 0; k < HD; k++) acc = fmaf(xs[r][k], Wcls[k*HD + d], acc);
            featsT[d][r] = fmaxf(acc, 0.0f);
        }
    }
    __syncthreads();

    // phase 2: f_in / f_out for all 8 rows (f32x2 packed: pairs of rows)
    {
        float bi = bin[t], bo = bout[t];
        u64 ai01 = pack2(bi,bi), ai23 = ai01, ai45 = ai01, ai67 = ai01;
        u64 ao01 = pack2(bo,bo), ao23 = ao01, ao45 = ao01, ao67 = ao01;
        #pragma unroll 4
        for (int k = 0; k < HD; k++) {
            float win  = Win [k*IDM + t];
            float wout = Wout[k*IDM + t];
            u64 wi = pack2(win, win), wo = pack2(wout, wout);
            const ulonglong2* fp = (const ulonglong2*)&featsT[k][0];
            ulonglong2 fA = fp[0], fB = fp[1];
            ai01 = fma2(fA.x, wi, ai01);  ao01 = fma2(fA.x, wo, ao01);
            ai23 = fma2(fA.y, wi, ai23);  ao23 = fma2(fA.y, wo, ao23);
            ai45 = fma2(fB.x, wi, ai45);  ao45 = fma2(fB.x, wo, ao45);
            ai67 = fma2(fB.y, wi, ai67);  ao67 = fma2(fB.y, wo, ao67);
        }
        float wp0 = Wpos[t], wp1 = Wpos[IDM + t], bp = bpos[t];
        float pe[RPB];
        #pragma unroll
        for (int r = 0; r < RPB; r++) pe[r] = fmaf(p0s[r], wp0, p1s[r] * wp1);
        u64 bp2  = pack2(bp, bp);
        u64 pe01 = pack2(pe[0], pe[1]), pe23 = pack2(pe[2], pe[3]);
        u64 pe45 = pack2(pe[4], pe[5]), pe67 = pack2(pe[6], pe[7]);
        u64* arow = (u64*)&ApreT[t][0];
        u64* brow = (u64*)&BpreT[t][0];
        arow[0] = add2(ai01, add2(pe01, bp2));
        arow[1] = add2(ai23, add2(pe23, bp2));
        arow[2] = add2(ai45, add2(pe45, bp2));
        arow[3] = add2(ai67, add2(pe67, bp2));
        brow[0] = add2(ao01, pe01);
        brow[1] = add2(ao23, pe23);
        brow[2] = add2(ao45, pe45);
        brow[3] = add2(ao67, pe67);
    }
    __syncthreads();

    // phase 3: U = Apre @ We1 + be1, V = Bpre @ We1 (f32x2 packed)
    float uu[RPB], vv[RPB];
    {
        float b1 = be1[t];
        u64 u01 = pack2(b1,b1), u23 = u01, u45 = u01, u67 = u01;
        u64 v01 = 0ULL, v23 = 0ULL, v45 = 0ULL, v67 = 0ULL;
        #pragma unroll 4
        for (int k = 0; k < IDM; k++) {
            float w = We1[k*IDM + t];
            u64 w2 = pack2(w, w);
            const ulonglong2* ap = (const ulonglong2*)&ApreT[k][0];
            const ulonglong2* cp = (const ulonglong2*)&BpreT[k][0];
            ulonglong2 aA = ap[0], aB = ap[1];
            ulonglong2 cA = cp[0], cB = cp[1];
            u01 = fma2(aA.x, w2, u01);  v01 = fma2(cA.x, w2, v01);
            u23 = fma2(aA.y, w2, u23);  v23 = fma2(cA.y, w2, v23);
            u45 = fma2(aB.x, w2, u45);  v45 = fma2(cB.x, w2, v45);
            u67 = fma2(aB.y, w2, u67);  v67 = fma2(cB.y, w2, v67);
        }
        u64 is2 = pack2(INV_SQRT2, INV_SQRT2);
        u01 = mul2(u01, is2); u23 = mul2(u23, is2);
        u45 = mul2(u45, is2); u67 = mul2(u67, is2);
        v01 = mul2(v01, is2); v23 = mul2(v23, is2);
        v45 = mul2(v45, is2); v67 = mul2(v67, is2);
        unpack2(u01, uu[0], uu[1]); unpack2(u23, uu[2], uu[3]);
        unpack2(u45, uu[4], uu[5]); unpack2(u67, uu[6], uu[7]);
        unpack2(v01, vv[0], vv[1]); unpack2(v23, vv[2], vv[3]);
        unpack2(v45, vv[4], vv[5]); unpack2(v67, vv[6], vv[7]);
    }

    float w2s = We2[t] * INV_SQRT2;
    #pragma unroll
    for (int r = 0; r < RPB; r++) {
        g_U2[(row0 + r)*IDM + t] = uu[r];
        g_V2[(row0 + r)*IDM + t] = vv[r];
        float su = uu[r] * w2s, sv = vv[r] * w2s;
        #pragma unroll
        for (int o = 16; o; o >>= 1) {
            su += __shfl_xor_sync(0xffffffffu, su, o);
            sv += __shfl_xor_sync(0xffffffffu, sv, o);
        }
        if (lane == 0) { partU[wid][r] = su; partV[wid][r] = sv; }
    }
    __syncthreads();
    if (t < RPB)
        g_SU[row0 + t] = partU[0][t] + partU[1][t] + partU[2][t] + partU[3][t];
    else if (t < 2*RPB) {
        int r = t - RPB;
        g_SV[row0 + r] = partV[0][r] + partV[1][r] + partV[2][r] + partV[3][r];
    }
}

// ---------------------------------------------------------------------------
// Main: 4 columns per block, 4 split-warps per column (512 threads).
// Batch-8 entries per warp iteration with a segmented butterfly reduce
// (9 shuffles per 8 entries instead of 5 per entry).
// ---------------------------------------------------------------------------
__global__ __launch_bounds__(512, 2) void main_kernel(
    const float* __restrict__ cls, const int* __restrict__ aid,
    const float* __restrict__ emb,
    const float* __restrict__ We2, const float* __restrict__ be2,
    const float* __restrict__ Wn1, const float* __restrict__ bn1,
    const float* __restrict__ Wn2, const float* __restrict__ bn2,
    const float* __restrict__ Wh,  const float* __restrict__ bh,
    float* __restrict__ out)
{
    __shared__ float cls_s[NN], ang_s[NN], su_s[NN];
    __shared__ int   id_s[NN];
    __shared__ unsigned short list_s[CPB][NN];
    __shared__ int   cnt_s[CPB];
    __shared__ float pmax_s[CPB][SPLIT];
    __shared__ float n1_s[CPB][HD];

    int t = threadIdx.x, lane = t & 31, w = t >> 5;
    int col = w >> 2, sw = w & 3;
    int g0 = blockIdx.x * CPB;
    int b  = g0 >> 9;                  // 128 blocks per batch, never straddles

    for (int i = t; i < NN; i += 512) {
        cls_s[i] = cls[b*NN + i];
        ang_s[i] = emb[(b*NN + i)*2] * PI_F;
        id_s[i]  = aid[b*NN + i];
        su_s[i]  = g_SU[b*NN + i];
    }
    __syncthreads();

    int g = g0 + col;
    int j = g & 511;
    float cj = cls_s[j];
    bool alive = (cj >= 0.4f);         // sigmoid(-1e6) == 0 in f32

    // one warp per column builds the compacted neighbor list
    if (sw == 0) {
        int cnt = 0;
        if (alive) {
            float aj  = ang_s[j];
            int   idj = id_s[j];
            unsigned short* lst = list_s[col];
            for (int c = 0; c < NN; c += 32) {
                int i = c + lane;
                float ci = cls_s[i];
                bool p = (fabsf(ang_s[i] - aj) < 0.5f) &&
                         ((ci > cj) || ((ci == cj) && (id_s[i] > idj)));
                unsigned m = __ballot_sync(0xffffffffu, p);
                if (p) lst[cnt + __popc(m & ((1u << lane) - 1u))] = (unsigned short)i;
                cnt += __popc(m);
            }
        }
        if (lane == 0) cnt_s[col] = cnt;
    }
    __syncthreads();

    float runmax = 0.0f;               // diagonal guarantees a 0 entry
    int cnt = cnt_s[col];

    if (alive && cnt > 0) {
        float4 v4  = *(const float4*)(g_V2 + (size_t)g*IDM + lane*4);
        float4 w2r = *(const float4*)(We2 + lane*4);
        float w2sx = w2r.x*INV_SQRT2, w2sy = w2r.y*INV_SQRT2;
        float w2sz = w2r.z*INV_SQRT2, w2sw = w2r.w*INV_SQRT2;
        float cconst = be2[0] - g_SV[g];
        const float* Ub = g_U2 + (size_t)b*NN*IDM + lane*4;
        const unsigned short* lst = list_s[col];
        int elane = ((lane >> 2) & 1) | (((lane >> 3) & 1) << 1) | (((lane >> 4) & 1) << 2);
        bool hi4 = lane & 16, hi3 = lane & 8, hi2 = lane & 4;

        for (int base = 8*sw; base < cnt; base += 8*SPLIT) {
            float p[8];
            // two half-batches of 4 to bound live registers while keeping MLP
            #pragma unroll
            for (int h = 0; h < 2; h++) {
                int i0 = lst[min(base + 4*h + 0, cnt-1)];
                int i1 = lst[min(base + 4*h + 1, cnt-1)];
                int i2 = lst[min(base + 4*h + 2, cnt-1)];
                int i3 = lst[min(base + 4*h + 3, cnt-1)];
                float4 u0 = *(const float4*)(Ub + i0*IDM);
                float4 u1 = *(const float4*)(Ub + i1*IDM);
                float4 u2 = *(const float4*)(Ub + i2*IDM);
                float4 u3 = *(const float4*)(Ub + i3*IDM);
                float4 uu[4] = {u0, u1, u2, u3};
                #pragma unroll
                for (int e = 0; e < 4; e++) {
                    float dx = uu[e].x - v4.x, dy = uu[e].y - v4.y;
                    float dz = uu[e].z - v4.z, dw = uu[e].w - v4.w;
                    float ex = fast_tanh(dx * fmaf(ERF_C1, dx*dx, ERF_C0));
                    float ey = fast_tanh(dy * fmaf(ERF_C1, dy*dy, ERF_C0));
                    float ez = fast_tanh(dz * fmaf(ERF_C1, dz*dz, ERF_C0));
                    float ew = fast_tanh(dw * fmaf(ERF_C1, dw*dw, ERF_C0));
                    float s;
                    s = (dx * w2sx) * ex;
                    s = fmaf(dy * w2sy, ey, s);
                    s = fmaf(dz * w2sz, ez, s);
                    s = fmaf(dw * w2sw, ew, s);
                    p[4*h + e] = s;
                }
            }
            // segmented butterfly: 8 sums across 32 lanes in 9 shuffles
            float q0 = (hi4 ? p[4] : p[0]) + __shfl_xor_sync(0xffffffffu, hi4 ? p[0] : p[4], 16);
            float q1 = (hi4 ? p[5] : p[1]) + __shfl_xor_sync(0xffffffffu, hi4 ? p[1] : p[5], 16);
            float q2 = (hi4 ? p[6] : p[2]) + __shfl_xor_sync(0xffffffffu, hi4 ? p[2] : p[6], 16);
            float q3 = (hi4 ? p[7] : p[3]) + __shfl_xor_sync(0xffffffffu, hi4 ? p[3] : p[7], 16);
            float r0 = (hi3 ? q2 : q0) + __shfl_xor_sync(0xffffffffu, hi3 ? q0 : q2, 8);
            float r1 = (hi3 ? q3 : q1) + __shfl_xor_sync(0xffffffffu, hi3 ? q1 : q3, 8);
            float s  = (hi2 ? r1 : r0) + __shfl_xor_sync(0xffffffffu, hi2 ? r0 : r1, 4);
            s += __shfl_xor_sync(0xffffffffu, s, 2);
            s += __shfl_xor_sync(0xffffffffu, s, 1);
            // this lane's entry
            int gidx = base + elane;
            int idxl = lst[min(gidx, cnt-1)];
            float extra = (gidx < cnt) ? (su_s[idxl] + cconst) : -3e38f;
            runmax = fmaxf(runmax, s + extra);
        }
        #pragma unroll
        for (int o = 16; o; o >>= 1)
            runmax = fmaxf(runmax, __shfl_xor_sync(0xffffffffu, runmax, o));
    }
    if (lane == 0) pmax_s[col][sw] = runmax;
    __syncthreads();

    // final: one warp per column does the node MLP
    if (sw == 0) {
        if (!alive) {
            if (lane == 0) out[g] = 0.0f;
        } else {
            float nm = fmaxf(fmaxf(pmax_s[col][0], pmax_s[col][1]),
                             fmaxf(pmax_s[col][2], pmax_s[col][3]));
            float n1a = fmaxf(fmaf(nm, Wn1[lane],      bn1[lane]),      0.0f);
            float n1b = fmaxf(fmaf(nm, Wn1[lane + 32], bn1[lane + 32]), 0.0f);
            n1_s[col][lane]      = n1a;
            n1_s[col][lane + 32] = n1b;
            __syncwarp();
            float acc0 = bn2[lane], acc1 = bn2[lane + 32];
            #pragma unroll 8
            for (int k = 0; k < HD; k++) {
                float f = n1_s[col][k];
                acc0 = fmaf(f, Wn2[k*HD + lane],      acc0);
                acc1 = fmaf(f, Wn2[k*HD + lane + 32], acc1);
            }
            acc0 = fmaxf(acc0, 0.0f);
            acc1 = fmaxf(acc1, 0.0f);
            float part = fmaf(acc0, Wh[lane], acc1 * Wh[lane + 32]);
            #pragma unroll
            for (int o = 16; o; o >>= 1) part += __shfl_xor_sync(0xffffffffu, part, o);
            if (lane == 0) {
                float lg = part + bh[0];
                out[g] = 1.0f / (1.0f + expf(-lg));
            }
        }
    }
}

extern "C" void kernel_launch(void* const* d_in, const int* in_sizes, int n_in,
                              void* d_out, int out_size) {
    const float* bf   = (const float*)d_in[0];
    const float* cls  = (const float*)d_in[1];
    const int*   aid  = (const int*)  d_in[2];
    const float* emb  = (const float*)d_in[3];
    const float* Wcls = (const float*)d_in[4];
    const float* bcls = (const float*)d_in[5];
    const float* Wpos = (const float*)d_in[6];
    const float* bpos = (const float*)d_in[7];
    const float* Win  = (const float*)d_in[8];
    const float* bin  = (const float*)d_in[9];
    const float* Wout = (const float*)d_in[10];
    const float* bout = (const float*)d_in[11];
    const float* We1  = (const float*)d_in[12];
    const float* be1  = (const float*)d_in[13];
    const float* We2  = (const float*)d_in[14];
    const float* be2  = (const float*)d_in[15];
    const float* Wn1  = (const float*)d_in[16];
    const float* bn1  = (const float*)d_in[17];
    const float* Wn2  = (const float*)d_in[18];
    const float* bn2  = (const float*)d_in[19];
    const float* Wh   = (const float*)d_in[20];
    const float* bh   = (const float*)d_in[21];
    float* out = (float*)d_out;

    prep_kernel<<<(BB*NN)/RPB, 128>>>(bf, emb, Wcls, bcls, Wpos, bpos,
                                      Win, bin, Wout, bout, We1, be1, We2);
    main_kernel<<<(BB*NN)/CPB, 512>>>(cls, aid, emb, We2, be2,
                                      Wn1, bn1, Wn2, bn2, Wh, bh, out);
}